// round 5
// baseline (speedup 1.0000x reference)
#include <cuda_runtime.h>

#define BATCH 32
#define NBOX 300
#define HH 1024
#define WW 1024
#define NTOT (BATCH * NBOX)            /* 9600 */
#define RPB 8                          /* rows per warp-iteration (1 row/warp) */
#define GITER 8                        /* iterations per block */
#define BAND (RPB * GITER)             /* 64 rows per block */
#define CGROUPS (HH / BAND)            /* 16 -> grid 16x32 = 512 blocks */
#define NT 256

// Scratch (allocation-free device globals). Layout: [chunk][box] (coalesced).
__device__ float g_partial[CGROUPS * NTOT];  // 614 KB
__device__ float g_batch[BATCH];
__device__ int   g_bctr[BATCH];              // zero-initialized
__device__ int   g_ctr = 0;

// trunc-toward-zero + clamp, exactly matching the reference
__device__ __forceinline__ int4 box_meta(const float4 bb) {
    int x1 = (int)((bb.x - 0.5f * bb.z) * (float)WW);
    int x2 = (int)((bb.x + 0.5f * bb.z) * (float)WW);
    int y1 = (int)((bb.y - 0.5f * bb.w) * (float)HH);
    int y2 = (int)((bb.y + 0.5f * bb.w) * (float)HH);
    x1 = min(max(x1, 0), WW - 1);
    x2 = min(max(x2, 0), WW - 1);
    y1 = min(max(y1, 0), HH - 1);
    y2 = min(max(y2, 0), HH - 1);
    return make_int4(x1, x2, y1, y2);
}

// ---------------------------------------------------------------------------
// Single fused kernel. grid = (CGROUPS, BATCH) = (16, 32), block = 256.
// Phase A: stream 64 rows, prefix-scan, box partials  (all 512 blocks)
// Phase B: last block of each batch reduces its 300 boxes (32 blocks)
// Phase C: globally-last block sums 32 batch values -> scalar (1 block)
// ---------------------------------------------------------------------------
__global__ __launch_bounds__(NT, 2)
void main_kernel(const float* __restrict__ seg,
                 const float* __restrict__ boxes,
                 const float* __restrict__ conf,
                 float* __restrict__ out) {
    __shared__ __align__(16) float P[RPB][WW];   // 32 KB exclusive row prefixes

    const int t    = threadIdx.x;
    const int lane = t & 31;
    const int wid  = t >> 5;
    const int b    = blockIdx.y;
    const int Y0   = blockIdx.x * BAND;
    const int base = b * NBOX;

    const float4* __restrict__ bp = (const float4*)boxes;
    int4 bx0 = box_meta(bp[base + t]);                    // t < 256 < 300
    int4 bx1 = (t + NT < NBOX) ? box_meta(bp[base + t + NT])
                               : make_int4(0, 0, 0, 0);

    const float* segD = seg + (size_t)(b * 3 + 1) * HH * WW;
    const float* segF = seg + (size_t)(b * 3 + 2) * HH * WW;

    float4 dv[8], fv[8];
    {   // preload iteration 0
        const float4* dr = (const float4*)(segD + (size_t)(Y0 + wid) * WW);
        const float4* fr = (const float4*)(segF + (size_t)(Y0 + wid) * WW);
        #pragma unroll
        for (int i = 0; i < 8; ++i) {
            dv[i] = __ldcs(&dr[i * 32 + lane]);
            fv[i] = __ldcs(&fr[i * 32 + lane]);
        }
    }

    float a0 = 0.0f, a1 = 0.0f;

    for (int g = 0; g < GITER; ++g) {
        // ---- scan: row -> exclusive prefix in P[wid] (warp-local) ----
        float carry = 0.0f;
        #pragma unroll
        for (int i = 0; i < 8; ++i) {
            float e0 = fv[i].x - dv[i].x;
            float e1 = fv[i].y - dv[i].y;
            float e2 = fv[i].z - dv[i].z;
            float e3 = fv[i].w - dv[i].w;
            float s0 = e0, s1 = s0 + e1, s2 = s1 + e2, s3 = s2 + e3;

            float v = s3;
            #pragma unroll
            for (int o = 1; o < 32; o <<= 1) {
                float n = __shfl_up_sync(0xffffffffu, v, o);
                if (lane >= o) v += n;
            }
            float ex = carry + (v - s3);
            carry += __shfl_sync(0xffffffffu, v, 31);
            *(float4*)&P[wid][i * 128 + lane * 4] =
                make_float4(ex, ex + s0, ex + s1, ex + s2);
        }
        __syncthreads();

        // ---- issue next band's loads (in flight during gather) ----
        if (g + 1 < GITER) {
            const int yn = Y0 + (g + 1) * RPB + wid;
            const float4* dr = (const float4*)(segD + (size_t)yn * WW);
            const float4* fr = (const float4*)(segF + (size_t)yn * WW);
            #pragma unroll
            for (int i = 0; i < 8; ++i) {
                dv[i] = __ldcs(&dr[i * 32 + lane]);
                fv[i] = __ldcs(&fr[i * 32 + lane]);
            }
        }

        // ---- gather: box row-sums from P ----
        const int yb = Y0 + g * RPB;
        #pragma unroll
        for (int r = 0; r < RPB; ++r) {
            const int yy = yb + r;
            if (yy >= bx0.z && yy < bx0.w) a0 += P[r][bx0.y] - P[r][bx0.x];
            if (yy >= bx1.z && yy < bx1.w) a1 += P[r][bx1.y] - P[r][bx1.x];
        }
        __syncthreads();
    }

    // Coalesced partial write: [chunk][box]
    g_partial[blockIdx.x * NTOT + base + t] = a0;
    if (t + NT < NBOX) g_partial[blockIdx.x * NTOT + base + t + NT] = a1;

    // ---- Phase B: last chunk-block of this batch reduces its boxes ----
    __shared__ int amLastBatch;
    __threadfence();
    if (t == 0) amLastBatch = (atomicAdd(&g_bctr[b], 1) == CGROUPS - 1);
    __syncthreads();
    if (!amLastBatch) return;
    __threadfence();

    float val = 0.0f;
    #pragma unroll
    for (int jj = 0; jj < 2; ++jj) {
        const int j = t + jj * NT;
        if (j < NBOX) {
            float s = 0.0f;
            #pragma unroll
            for (int c = 0; c < CGROUPS; ++c)
                s += g_partial[c * NTOT + base + j];    // L2-hot, coalesced
            int4 m = (jj == 0) ? bx0 : bx1;
            float cf = conf[base + j];
            bool valid = (cf >= 0.3f) && (m.y > m.x) && (m.w > m.z);
            float area = (float)((m.w - m.z) * (m.y - m.x));
            val += valid ? fmaxf(s, 0.0f) * (cf / area) : 0.0f;
        }
    }
    // Block reduction (fixed order -> deterministic)
    __shared__ float red[NT / 32];
    #pragma unroll
    for (int o = 16; o; o >>= 1) val += __shfl_down_sync(0xffffffffu, val, o);
    if (lane == 0) red[wid] = val;
    __syncthreads();
    if (t < 32) {
        float v = (t < NT / 32) ? red[t] : 0.0f;
        #pragma unroll
        for (int o = 4; o; o >>= 1) v += __shfl_down_sync(0xffffffffu, v, o);
        if (t == 0) {
            g_batch[b] = v;
            g_bctr[b] = 0;                       // reset for next graph replay
        }
    }

    // ---- Phase C: globally-last batch-finisher writes the scalar ----
    __shared__ int amLastGlobal;
    __threadfence();
    if (t == 0) amLastGlobal = (atomicAdd(&g_ctr, 1) == BATCH - 1);
    __syncthreads();
    if (!amLastGlobal) return;
    __threadfence();

    if (t < 32) {
        float v = g_batch[t];
        #pragma unroll
        for (int o = 16; o; o >>= 1) v += __shfl_down_sync(0xffffffffu, v, o);
        if (t == 0) {
            out[0] = v / (float)NTOT;
            g_ctr = 0;                           // reset for next replay
        }
    }
}

extern "C" void kernel_launch(void* const* d_in, const int* in_sizes, int n_in,
                              void* d_out, int out_size) {
    const float* boxes = (const float*)d_in[0];  // (32,300,4)
    const float* conf  = (const float*)d_in[1];  // (32,300)
    const float* seg   = (const float*)d_in[2];  // (32,3,1024,1024)

    dim3 grid(CGROUPS, BATCH);
    main_kernel<<<grid, NT>>>(seg, boxes, conf, (float*)d_out);
}

// round 6
// speedup vs baseline: 1.0006x; 1.0006x over previous
#include <cuda_runtime.h>

#define BATCH 32
#define NBOX 300
#define HH 1024
#define WW 1024
#define NTOT (BATCH * NBOX)            /* 9600 */
#define RPB 8                          /* rows per iteration, one per warp */
#define GITER 8                        /* iterations per block */
#define BAND (RPB * GITER)             /* 64 rows per block */
#define CGROUPS (HH / BAND)            /* 16 -> grid 16x32 = 512 blocks */
#define NT 256
#define RED_BLOCKS ((NTOT + NT - 1) / NT)  /* 38 */

// Scratch (allocation-free device globals). Layout: [chunk][box] (coalesced).
__device__ float g_partial[CGROUPS * NTOT];  // 614 KB
__device__ float g_blk[RED_BLOCKS];
__device__ int   g_ctr = 0;

// trunc-toward-zero + clamp, exactly matching the reference
__device__ __forceinline__ int4 box_meta(const float4 bb) {
    int x1 = (int)((bb.x - 0.5f * bb.z) * (float)WW);
    int x2 = (int)((bb.x + 0.5f * bb.z) * (float)WW);
    int y1 = (int)((bb.y - 0.5f * bb.w) * (float)HH);
    int y2 = (int)((bb.y + 0.5f * bb.w) * (float)HH);
    x1 = min(max(x1, 0), WW - 1);
    x2 = min(max(x2, 0), WW - 1);
    y1 = min(max(y1, 0), HH - 1);
    y2 = min(max(y2, 0), HH - 1);
    return make_int4(x1, x2, y1, y2);
}

// ---------------------------------------------------------------------------
// Main kernel: band of 64 rows per block, warp-per-row scan.
// grid = (16, 32) = 512 blocks, block = 256, target 4 blocks/SM (<=64 regs).
// No manual prefetch: occupancy (32 warps/SM) provides the latency overlap.
// ---------------------------------------------------------------------------
__global__ __launch_bounds__(NT, 4)
void main_kernel(const float* __restrict__ seg, const float* __restrict__ boxes) {
    __shared__ __align__(16) float P[RPB][WW];   // 32 KB exclusive row prefixes

    const int t    = threadIdx.x;
    const int lane = t & 31;
    const int wid  = t >> 5;
    const int b    = blockIdx.y;
    const int Y0   = blockIdx.x * BAND;
    const int base = b * NBOX;

    const float4* __restrict__ bp = (const float4*)boxes;
    int4 bx0 = box_meta(bp[base + t]);                    // t < 256 < 300
    int4 bx1 = (t + NT < NBOX) ? box_meta(bp[base + t + NT])
                               : make_int4(0, 0, 0, 0);

    const float* segD = seg + (size_t)(b * 3 + 1) * HH * WW;
    const float* segF = seg + (size_t)(b * 3 + 2) * HH * WW;

    float a0 = 0.0f, a1 = 0.0f;

    for (int g = 0; g < GITER; ++g) {
        const int y = Y0 + g * RPB + wid;        // this warp's row
        const float4* dr = (const float4*)(segD + (size_t)y * WW);
        const float4* fr = (const float4*)(segF + (size_t)y * WW);

        // ---- fused diff + cyclic exclusive prefix (warp-local) ----
        float carry = 0.0f;
        #pragma unroll
        for (int i = 0; i < 8; ++i) {
            float4 d = __ldcs(&dr[i * 32 + lane]);
            float4 f = __ldcs(&fr[i * 32 + lane]);
            float e0 = f.x - d.x;
            float e1 = f.y - d.y;
            float e2 = f.z - d.z;
            float e3 = f.w - d.w;
            float s0 = e0, s1 = s0 + e1, s2 = s1 + e2, s3 = s2 + e3;

            float v = s3;                        // warp scan of chunk sums
            #pragma unroll
            for (int o = 1; o < 32; o <<= 1) {
                float n = __shfl_up_sync(0xffffffffu, v, o);
                if (lane >= o) v += n;
            }
            float ex = carry + (v - s3);
            carry += __shfl_sync(0xffffffffu, v, 31);
            *(float4*)&P[wid][i * 128 + lane * 4] =
                make_float4(ex, ex + s0, ex + s1, ex + s2);
        }
        __syncthreads();

        // ---- gather: box row-sums from P ----
        const int yb = Y0 + g * RPB;
        #pragma unroll
        for (int r = 0; r < RPB; ++r) {
            const int yy = yb + r;
            if (yy >= bx0.z && yy < bx0.w) a0 += P[r][bx0.y] - P[r][bx0.x];
            if (yy >= bx1.z && yy < bx1.w) a1 += P[r][bx1.y] - P[r][bx1.x];
        }
        __syncthreads();
    }

    g_partial[blockIdx.x * NTOT + base + t] = a0;
    if (t + NT < NBOX) g_partial[blockIdx.x * NTOT + base + t + NT] = a1;
}

// ---------------------------------------------------------------------------
// Reduction (PDL secondary): waits on main via grid dependency, then
// per-box chunk sum + relu*weight + deterministic grid reduction.
// ---------------------------------------------------------------------------
__global__ __launch_bounds__(NT)
void reduce_kernel(const float* __restrict__ boxes,
                   const float* __restrict__ conf,
                   float* __restrict__ out) {
    cudaGridDependencySynchronize();             // main's writes now visible

    const int t = threadIdx.x;
    const int i = blockIdx.x * NT + t;

    float val = 0.0f;
    if (i < NTOT) {
        float s = 0.0f;
        #pragma unroll
        for (int c = 0; c < CGROUPS; ++c)
            s += g_partial[c * NTOT + i];
        float4 bb = ((const float4*)boxes)[i];
        int4 m = box_meta(bb);
        float cf = conf[i];
        bool valid = (cf >= 0.3f) && (m.y > m.x) && (m.w > m.z);
        float area = (float)((m.w - m.z) * (m.y - m.x));
        val = valid ? fmaxf(s, 0.0f) * (cf / area) : 0.0f;
    }

    __shared__ float red[NT / 32];
    #pragma unroll
    for (int o = 16; o; o >>= 1) val += __shfl_down_sync(0xffffffffu, val, o);
    if ((t & 31) == 0) red[t >> 5] = val;
    __syncthreads();
    if (t < 32) {
        float v = (t < NT / 32) ? red[t] : 0.0f;
        #pragma unroll
        for (int o = 4; o; o >>= 1) v += __shfl_down_sync(0xffffffffu, v, o);
        if (t == 0) g_blk[blockIdx.x] = v;
    }

    __shared__ int amLast;
    __threadfence();
    if (t == 0) amLast = (atomicAdd(&g_ctr, 1) == gridDim.x - 1);
    __syncthreads();
    if (amLast) {
        __threadfence();
        if (t < 32) {
            float v = g_blk[t];                       // t < 32 < 38
            if (t + 32 < RED_BLOCKS) v += g_blk[t + 32];
            #pragma unroll
            for (int o = 16; o; o >>= 1) v += __shfl_down_sync(0xffffffffu, v, o);
            if (t == 0) {
                out[0] = v / (float)NTOT;
                g_ctr = 0;                            // reset for next replay
            }
        }
    }
}

extern "C" void kernel_launch(void* const* d_in, const int* in_sizes, int n_in,
                              void* d_out, int out_size) {
    const float* boxes = (const float*)d_in[0];  // (32,300,4)
    const float* conf  = (const float*)d_in[1];  // (32,300)
    const float* seg   = (const float*)d_in[2];  // (32,3,1024,1024)

    dim3 grid(CGROUPS, BATCH);
    main_kernel<<<grid, NT>>>(seg, boxes);

    // PDL: overlap reduce's launch/ramp with main's tail.
    cudaLaunchConfig_t cfg = {};
    cfg.gridDim  = dim3(RED_BLOCKS, 1, 1);
    cfg.blockDim = dim3(NT, 1, 1);
    cfg.dynamicSmemBytes = 0;
    cfg.stream = 0;
    cudaLaunchAttribute attr[1];
    attr[0].id = cudaLaunchAttributeProgrammaticStreamSerialization;
    attr[0].val.programmaticStreamSerializationAllowed = 1;
    cfg.attrs = attr;
    cfg.numAttrs = 1;
    cudaLaunchKernelEx(&cfg, reduce_kernel, boxes, conf, (float*)d_out);
}

// round 9
// speedup vs baseline: 1.0329x; 1.0322x over previous
#include <cuda_runtime.h>

#define BATCH 32
#define NBOX 300
#define HH 1024
#define WW 1024
#define NTOT (BATCH * NBOX)            /* 9600 */
#define RPB 8                          /* rows per iteration, one per warp */
#define GITER 8                        /* iterations per block */
#define BAND (RPB * GITER)             /* 64 rows per block */
#define CGROUPS (HH / BAND)            /* 16 -> grid 16x32 = 512 blocks */
#define NT 256
#define RED_BLOCKS ((NTOT + NT - 1) / NT)  /* 38 */

// Scratch (allocation-free device globals). Layout: [chunk][box] (coalesced).
__device__ float g_partial[CGROUPS * NTOT];  // 614 KB
__device__ float g_blk[RED_BLOCKS];
__device__ int   g_ctr = 0;

// trunc-toward-zero + clamp, exactly matching the reference
__device__ __forceinline__ int4 box_meta(const float4 bb) {
    int x1 = (int)((bb.x - 0.5f * bb.z) * (float)WW);
    int x2 = (int)((bb.x + 0.5f * bb.z) * (float)WW);
    int y1 = (int)((bb.y - 0.5f * bb.w) * (float)HH);
    int y2 = (int)((bb.y + 0.5f * bb.w) * (float)HH);
    x1 = min(max(x1, 0), WW - 1);
    x2 = min(max(x2, 0), WW - 1);
    y1 = min(max(y1, 0), HH - 1);
    y2 = min(max(y2, 0), HH - 1);
    return make_int4(x1, x2, y1, y2);
}

// ---------------------------------------------------------------------------
// Main kernel: band of 64 rows per block, warp-per-row scan, deep prefetch.
// Scan is latency-optimized: shuffle rounds interleaved across all 8 chunks.
// grid = (16, 32) = 512 blocks, block = 256, occ 2 (128 regs).
// ---------------------------------------------------------------------------
__global__ __launch_bounds__(NT, 2)
void main_kernel(const float* __restrict__ seg, const float* __restrict__ boxes) {
    __shared__ __align__(16) float P[RPB][WW];   // 32 KB exclusive row prefixes

    const int t    = threadIdx.x;
    const int lane = t & 31;
    const int wid  = t >> 5;
    const int b    = blockIdx.y;
    const int Y0   = blockIdx.x * BAND;
    const int base = b * NBOX;

    const float4* __restrict__ bp = (const float4*)boxes;
    int4 bx0 = box_meta(bp[base + t]);                    // t < 256 < 300
    int4 bx1 = (t + NT < NBOX) ? box_meta(bp[base + t + NT])
                               : make_int4(0, 0, 0, 0);

    const float* segD = seg + (size_t)(b * 3 + 1) * HH * WW;
    const float* segF = seg + (size_t)(b * 3 + 2) * HH * WW;

    float4 dv[8], fv[8];
    {   // preload iteration 0
        const float4* dr = (const float4*)(segD + (size_t)(Y0 + wid) * WW);
        const float4* fr = (const float4*)(segF + (size_t)(Y0 + wid) * WW);
        #pragma unroll
        for (int i = 0; i < 8; ++i) {
            dv[i] = __ldcs(&dr[i * 32 + lane]);
            fv[i] = __ldcs(&fr[i * 32 + lane]);
        }
    }

    float a0 = 0.0f, a1 = 0.0f;

    for (int g = 0; g < GITER; ++g) {
        // ---- phase 0: diffs + thread-local prefixes (frees dv/fv) ----
        float p0[8], p1[8], p2[8], s3[8], v[8];
        #pragma unroll
        for (int i = 0; i < 8; ++i) {
            float e0 = fv[i].x - dv[i].x;
            float e1 = fv[i].y - dv[i].y;
            float e2 = fv[i].z - dv[i].z;
            float e3 = fv[i].w - dv[i].w;
            p0[i] = e0;
            p1[i] = e0 + e1;
            p2[i] = p1[i] + e2;
            s3[i] = p2[i] + e3;
            v[i]  = s3[i];
        }

        // ---- phase 1: warp scan, rounds interleaved across chunks ----
        #pragma unroll
        for (int o = 1; o < 32; o <<= 1) {
            #pragma unroll
            for (int i = 0; i < 8; ++i) {
                float n = __shfl_up_sync(0xffffffffu, v[i], o);
                if (lane >= o) v[i] += n;
            }
        }

        // ---- phase 2: chunk totals (independent broadcasts) + carry chain ----
        float tot[8];
        #pragma unroll
        for (int i = 0; i < 8; ++i)
            tot[i] = __shfl_sync(0xffffffffu, v[i], 31);

        float carry = 0.0f;
        #pragma unroll
        for (int i = 0; i < 8; ++i) {
            float ex = carry + (v[i] - s3[i]);   // exclusive prefix, this chunk
            *(float4*)&P[wid][i * 128 + lane * 4] =
                make_float4(ex, ex + p0[i], ex + p1[i], ex + p2[i]);
            carry += tot[i];
        }

        // ---- issue next band's loads BEFORE the barrier (max lead time) ----
        if (g + 1 < GITER) {
            const int yn = Y0 + (g + 1) * RPB + wid;
            const float4* dr = (const float4*)(segD + (size_t)yn * WW);
            const float4* fr = (const float4*)(segF + (size_t)yn * WW);
            #pragma unroll
            for (int i = 0; i < 8; ++i) {
                dv[i] = __ldcs(&dr[i * 32 + lane]);
                fv[i] = __ldcs(&fr[i * 32 + lane]);
            }
        }
        __syncthreads();

        // ---- gather: box row-sums from P ----
        const int yb = Y0 + g * RPB;
        #pragma unroll
        for (int r = 0; r < RPB; ++r) {
            const int yy = yb + r;
            if (yy >= bx0.z && yy < bx0.w) a0 += P[r][bx0.y] - P[r][bx0.x];
            if (yy >= bx1.z && yy < bx1.w) a1 += P[r][bx1.y] - P[r][bx1.x];
        }
        __syncthreads();
    }

    g_partial[blockIdx.x * NTOT + base + t] = a0;
    if (t + NT < NBOX) g_partial[blockIdx.x * NTOT + base + t + NT] = a1;

    // PDL: allow the dependent reduce kernel in before our epilogue/drain.
    cudaTriggerProgrammaticLaunchCompletion();
}

// ---------------------------------------------------------------------------
// Reduction (PDL secondary): waits on main via grid dependency, then
// per-box chunk sum + relu*weight + deterministic grid reduction.
// ---------------------------------------------------------------------------
__global__ __launch_bounds__(NT)
void reduce_kernel(const float* __restrict__ boxes,
                   const float* __restrict__ conf,
                   float* __restrict__ out) {
    cudaGridDependencySynchronize();             // main's partial writes visible

    const int t = threadIdx.x;
    const int i = blockIdx.x * NT + t;

    float val = 0.0f;
    if (i < NTOT) {
        float s = 0.0f;
        #pragma unroll
        for (int c = 0; c < CGROUPS; ++c)
            s += g_partial[c * NTOT + i];
        float4 bb = ((const float4*)boxes)[i];
        int4 m = box_meta(bb);
        float cf = conf[i];
        bool valid = (cf >= 0.3f) && (m.y > m.x) && (m.w > m.z);
        float area = (float)((m.w - m.z) * (m.y - m.x));
        val = valid ? fmaxf(s, 0.0f) * (cf / area) : 0.0f;
    }

    __shared__ float red[NT / 32];
    #pragma unroll
    for (int o = 16; o; o >>= 1) val += __shfl_down_sync(0xffffffffu, val, o);
    if ((t & 31) == 0) red[t >> 5] = val;
    __syncthreads();
    if (t < 32) {
        float v = (t < NT / 32) ? red[t] : 0.0f;
        #pragma unroll
        for (int o = 4; o; o >>= 1) v += __shfl_down_sync(0xffffffffu, v, o);
        if (t == 0) g_blk[blockIdx.x] = v;
    }

    __shared__ int amLast;
    __threadfence();
    if (t == 0) amLast = (atomicAdd(&g_ctr, 1) == gridDim.x - 1);
    __syncthreads();
    if (amLast) {
        __threadfence();
        if (t < 32) {
            float v = g_blk[t];                       // t < 32 < 38
            if (t + 32 < RED_BLOCKS) v += g_blk[t + 32];
            #pragma unroll
            for (int o = 16; o; o >>= 1) v += __shfl_down_sync(0xffffffffu, v, o);
            if (t == 0) {
                out[0] = v / (float)NTOT;
                g_ctr = 0;                            // reset for next replay
            }
        }
    }
}

extern "C" void kernel_launch(void* const* d_in, const int* in_sizes, int n_in,
                              void* d_out, int out_size) {
    const float* boxes = (const float*)d_in[0];  // (32,300,4)
    const float* conf  = (const float*)d_in[1];  // (32,300)
    const float* seg   = (const float*)d_in[2];  // (32,3,1024,1024)

    dim3 grid(CGROUPS, BATCH);
    main_kernel<<<grid, NT>>>(seg, boxes);

    // PDL: overlap reduce's launch/ramp with main's tail.
    cudaLaunchConfig_t cfg = {};
    cfg.gridDim  = dim3(RED_BLOCKS, 1, 1);
    cfg.blockDim = dim3(NT, 1, 1);
    cfg.dynamicSmemBytes = 0;
    cfg.stream = 0;
    cudaLaunchAttribute attr[1];
    attr[0].id = cudaLaunchAttributeProgrammaticStreamSerialization;
    attr[0].val.programmaticStreamSerializationAllowed = 1;
    cfg.attrs = attr;
    cfg.numAttrs = 1;
    cudaLaunchKernelEx(&cfg, reduce_kernel, boxes, conf, (float*)d_out);
}